// round 14
// baseline (speedup 1.0000x reference)
#include <cuda_runtime.h>
#include <cstddef>

// ---------------------------------------------------------------------------
// GATv2 x2 on GB300.  kernel_launch = kernel launches ONLY.
// Sequence: count(1), scan(2), gemm1+scatter fused(3), agg1(4), gemm2(5),
// agg2(6).  (agg1 at position 4 => ncu captures it this round.)
// Self-loop seeding + deg/cnt zeroing folded into k_scan (replay-invariant:
// scan zeroes deg/cnt for the next replay after consuming them).
// ---------------------------------------------------------------------------

#define NMAX 100000
#define EMAX 1700032

__device__ float g_xl1[NMAX * 128];
__device__ float g_xr1[NMAX * 128];
__device__ float g_h  [NMAX * 128];
__device__ float g_xl2[NMAX * 64];
__device__ float g_xr2[NMAX * 64];
__device__ int   g_deg[NMAX];      // zero at launch start (invariant)
__device__ int   g_cnt[NMAX];      // zero before scatter (scan restores)
__device__ int   g_rowptr[NMAX + 1];
__device__ int   g_col[EMAX];

// --------------------------- CSR build -------------------------------------

// nvec = E/4 if vectorizable, else 0
__global__ void k_count(const int* __restrict__ dstE, int E, int nvec) {
    int t = blockIdx.x * blockDim.x + threadIdx.x;
    if (t < nvec) {
        int4 d = reinterpret_cast<const int4*>(dstE)[t];
        atomicAdd(&g_deg[d.x], 1);
        atomicAdd(&g_deg[d.y], 1);
        atomicAdd(&g_deg[d.z], 1);
        atomicAdd(&g_deg[d.w], 1);
    } else {
        int e = nvec * 4 + (t - nvec);
        if (e < E) atomicAdd(&g_deg[dstE[e]], 1);
    }
}

// exclusive scan of (deg+1) -> rowptr; afterwards zero deg & cnt for the
// next replay / for this launch's scatter.
__global__ void k_scan(int n) {
    __shared__ int wsum[32];
    __shared__ int carry;
    int t = threadIdx.x;
    if (t == 0) carry = 0;
    __syncthreads();
    for (int base = 0; base < n; base += 1024) {
        int i = base + t;
        int v = (i < n) ? (g_deg[i] + 1) : 0;    // +1 = self loop
        int x = v;
        #pragma unroll
        for (int off = 1; off < 32; off <<= 1) {
            int y = __shfl_up_sync(0xffffffffu, x, off);
            if ((t & 31) >= off) x += y;
        }
        if ((t & 31) == 31) wsum[t >> 5] = x;
        __syncthreads();
        if (t < 32) {
            int w = wsum[t];
            #pragma unroll
            for (int off = 1; off < 32; off <<= 1) {
                int y = __shfl_up_sync(0xffffffffu, w, off);
                if (t >= off) w += y;
            }
            wsum[t] = w;
        }
        __syncthreads();
        int incl = x + ((t >= 32) ? wsum[(t >> 5) - 1] : 0);
        if (i < n) {
            g_rowptr[i] = incl - v + carry;
            g_deg[i] = 0;          // restore invariant for next replay
            g_cnt[i] = 0;          // ready for this launch's scatter
        }
        __syncthreads();
        if (t == 1023) carry += incl;
        __syncthreads();
    }
    if (t == 0) g_rowptr[n] = carry;
}

__device__ __forceinline__ void csr_place(int s, int d) {
    int pos = g_rowptr[d] + atomicAdd(&g_cnt[d], 1);
    g_col[pos] = s;
}

// --------------------------- fused dense GEMM (+scatter plane) --------------
// y in [0, 2*NOUT/64): gemm planes (lr x colgroup).  If SCAT, y == 2*NOUT/64
// is the CSR scatter plane (grid-stride; latency-bound, coexists with the
// fma-bound gemm blocks).

template<int XSEL, int NOUT, bool SCAT>
__global__ void __launch_bounds__(128, 4)
k_gemm2(const float* __restrict__ Xarg,
        const float* __restrict__ WL, const float* __restrict__ WR,
        const float* __restrict__ BL, const float* __restrict__ BR, int n,
        const int* __restrict__ srcE, const int* __restrict__ dstE,
        int E, int nvec, int N) {
    constexpr int K = 128, KC = 64, NB = 64, TPR = 8;
    constexpr int RG = 128 / TPR;                        // 16 row groups
    constexpr int R = 8;
    constexpr int ROWS = RG * R;                         // 128 rows/block
    constexpr int CG = NOUT / NB;
    __shared__ float sW[KC][NB];          // 16 KB
    __shared__ float sx[ROWS][KC + 4];    // 34.8 KB

    if (SCAT && blockIdx.y == 2 * CG) {
        int total = nvec + N + (E - nvec * 4);
        int stride = gridDim.x * 128;
        for (int t = blockIdx.x * 128 + threadIdx.x; t < total; t += stride) {
            if (t < nvec) {
                int4 s = reinterpret_cast<const int4*>(srcE)[t];
                int4 d = reinterpret_cast<const int4*>(dstE)[t];
                csr_place(s.x, d.x);
                csr_place(s.y, d.y);
                csr_place(s.z, d.z);
                csr_place(s.w, d.w);
            } else {
                int u = t - nvec;
                if (u < N) csr_place(u, u);
                else {
                    int e = nvec * 4 + (u - N);
                    if (e < E) csr_place(srcE[e], dstE[e]);
                }
            }
        }
        return;
    }

    const float* X = (XSEL == 0) ? Xarg : g_h;
    int lr = blockIdx.y / CG;
    int cg = blockIdx.y % CG;
    const float* W    = lr ? WR : WL;
    const float* Bias = lr ? BR : BL;
    float* Y;
    if constexpr (XSEL == 0) Y = lr ? g_xr1 : g_xl1;
    else                     Y = lr ? g_xr2 : g_xl2;

    int tid = threadIdx.x;
    int colOff = cg * NB;
    int c0 = (tid % TPR) * 4;
    int rg = tid / TPR;                  // 0..15
    int base = blockIdx.x * ROWS;

    float4 bv0 = *reinterpret_cast<const float4*>(Bias + colOff + c0);
    float4 bv1 = *reinterpret_cast<const float4*>(Bias + colOff + c0 + 32);
    unsigned long long a0[R][2], a1[R][2];
    #pragma unroll
    for (int r = 0; r < R; r++) {
        asm("mov.b64 %0, {%1,%2};" : "=l"(a0[r][0]) : "f"(bv0.x), "f"(bv0.y));
        asm("mov.b64 %0, {%1,%2};" : "=l"(a0[r][1]) : "f"(bv0.z), "f"(bv0.w));
        asm("mov.b64 %0, {%1,%2};" : "=l"(a1[r][0]) : "f"(bv1.x), "f"(bv1.y));
        asm("mov.b64 %0, {%1,%2};" : "=l"(a1[r][1]) : "f"(bv1.z), "f"(bv1.w));
    }

    for (int kc = 0; kc < K; kc += KC) {
        __syncthreads();
        for (int i = tid; i < KC * NB / 4; i += 128) {
            int krow = (i * 4) / NB;
            int col  = (i * 4) % NB;
            *reinterpret_cast<float4*>(&sW[krow][col]) =
                *reinterpret_cast<const float4*>(W + (size_t)(kc + krow) * NOUT + colOff + col);
        }
        for (int i = tid; i < ROWS * (KC / 4); i += 128) {
            int r  = i / (KC / 4);
            int kk = (i % (KC / 4)) * 4;
            int row = base + r;
            float4 v = (row < n)
                ? *reinterpret_cast<const float4*>(X + (size_t)row * K + kc + kk)
                : make_float4(0.f, 0.f, 0.f, 0.f);
            *reinterpret_cast<float4*>(&sx[r][kk]) = v;
        }
        __syncthreads();
        #pragma unroll
        for (int k4 = 0; k4 < KC; k4 += 4) {
            float4 xv[R];
            #pragma unroll
            for (int r = 0; r < R; r++)
                xv[r] = *reinterpret_cast<const float4*>(&sx[rg + r * RG][k4]);
            #pragma unroll
            for (int kk = 0; kk < 4; kk++) {
                ulonglong2 w0 = *reinterpret_cast<const ulonglong2*>(&sW[k4 + kk][c0]);
                ulonglong2 w1 = *reinterpret_cast<const ulonglong2*>(&sW[k4 + kk][c0 + 32]);
                #pragma unroll
                for (int r = 0; r < R; r++) {
                    float xs = (kk == 0) ? xv[r].x : (kk == 1) ? xv[r].y
                             : (kk == 2) ? xv[r].z : xv[r].w;
                    unsigned long long x2;
                    asm("mov.b64 %0, {%1,%1};" : "=l"(x2) : "f"(xs));
                    asm("fma.rn.f32x2 %0, %1, %2, %0;" : "+l"(a0[r][0]) : "l"(x2), "l"(w0.x));
                    asm("fma.rn.f32x2 %0, %1, %2, %0;" : "+l"(a0[r][1]) : "l"(x2), "l"(w0.y));
                    asm("fma.rn.f32x2 %0, %1, %2, %0;" : "+l"(a1[r][0]) : "l"(x2), "l"(w1.x));
                    asm("fma.rn.f32x2 %0, %1, %2, %0;" : "+l"(a1[r][1]) : "l"(x2), "l"(w1.y));
                }
            }
        }
    }

    #pragma unroll
    for (int r = 0; r < R; r++) {
        int row = base + rg + r * RG;
        if (row < n) {
            float t0, t1, t2, t3;
            asm("mov.b64 {%0,%1}, %2;" : "=f"(t0), "=f"(t1) : "l"(a0[r][0]));
            asm("mov.b64 {%0,%1}, %2;" : "=f"(t2), "=f"(t3) : "l"(a0[r][1]));
            *reinterpret_cast<float4*>(Y + (size_t)row * NOUT + colOff + c0) =
                make_float4(t0, t1, t2, t3);
            asm("mov.b64 {%0,%1}, %2;" : "=f"(t0), "=f"(t1) : "l"(a1[r][0]));
            asm("mov.b64 {%0,%1}, %2;" : "=f"(t2), "=f"(t3) : "l"(a1[r][1]));
            *reinterpret_cast<float4*>(Y + (size_t)row * NOUT + colOff + c0 + 32) =
                make_float4(t0, t1, t2, t3);
        }
    }
}

// --------------------------- GATv2 aggregation ------------------------------
// Warp per destination node, software-pipelined: next batch's indices are
// loaded before computing the current batch, and next gathers issue before
// their consumption (one-iteration slack) -> gather latency overlapped.
// Scores are O(+-10) (glorot x unit-normal): exp without max-pass is safe.

__device__ __forceinline__ float lrelu(float e) {
    return (e > 0.f) ? e : 0.2f * e;
}

__global__ void k_agg1(const float* __restrict__ att, const float* __restrict__ bias,
                       int n) {
    int v    = (blockIdx.x * blockDim.x + threadIdx.x) >> 5;
    int lane = threadIdx.x & 31;
    if (v >= n) return;

    const float4* xl4 = reinterpret_cast<const float4*>(g_xl1);
    float4 xrv  = *reinterpret_cast<const float4*>(g_xr1 + (size_t)v * 128 + lane * 4);
    float4 attv = *reinterpret_cast<const float4*>(att + lane * 4);
    float4 acc  = make_float4(0.f, 0.f, 0.f, 0.f);
    float  den  = 0.f;

    int s0 = g_rowptr[v], s1 = g_rowptr[v + 1];

    auto score = [&](const float4& xv) -> float {
        float s;
        s = lrelu(xv.x + xrv.x) * attv.x;
        s = fmaf(lrelu(xv.y + xrv.y), attv.y, s);
        s = fmaf(lrelu(xv.z + xrv.z), attv.z, s);
        s = fmaf(lrelu(xv.w + xrv.w), attv.w, s);
        s += __shfl_xor_sync(0xffffffffu, s, 1);
        s += __shfl_xor_sync(0xffffffffu, s, 2);
        s += __shfl_xor_sync(0xffffffffu, s, 4);
        return __expf(s);
    };
    auto accum = [&](const float4& xv, float p) {
        den += p;
        acc.x = fmaf(p, xv.x, acc.x);
        acc.y = fmaf(p, xv.y, acc.y);
        acc.z = fmaf(p, xv.z, acc.z);
        acc.w = fmaf(p, xv.w, acc.w);
    };

    int j = s0;
    int nb4 = (s1 - s0) >> 2;
    if (nb4 > 0) {
        int i0 = g_col[j], i1 = g_col[j+1], i2 = g_col[j+2], i3 = g_col[j+3];
        float4 x0 = __ldg(&xl4[(size_t)i0 * 32 + lane]);
        float4 x1 = __ldg(&xl4[(size_t)i1 * 32 + lane]);
        float4 x2 = __ldg(&xl4[(size_t)i2 * 32 + lane]);
        float4 x3 = __ldg(&xl4[(size_t)i3 * 32 + lane]);
        for (int b = 1; b < nb4; b++) {
            j += 4;
            int n0 = g_col[j], n1 = g_col[j+1], n2 = g_col[j+2], n3 = g_col[j+3];
            float p0 = score(x0), p1 = score(x1), p2 = score(x2), p3 = score(x3);
            accum(x0, p0); accum(x1, p1); accum(x2, p2); accum(x3, p3);
            x0 = __ldg(&xl4[(size_t)n0 * 32 + lane]);
            x1 = __ldg(&xl4[(size_t)n1 * 32 + lane]);
            x2 = __ldg(&xl4[(size_t)n2 * 32 + lane]);
            x3 = __ldg(&xl4[(size_t)n3 * 32 + lane]);
        }
        float p0 = score(x0), p1 = score(x1), p2 = score(x2), p3 = score(x3);
        accum(x0, p0); accum(x1, p1); accum(x2, p2); accum(x3, p3);
        j += 4;
    }
    for (; j < s1; j++) {
        int src = g_col[j];
        float4 xv = __ldg(&xl4[(size_t)src * 32 + lane]);
        accum(xv, score(xv));
    }

    float4 bv = *reinterpret_cast<const float4*>(bias + lane * 4);
    float inv = 1.f / den;
    float4 r;
    r.x = fmaxf(fmaf(acc.x, inv, bv.x), 0.f);
    r.y = fmaxf(fmaf(acc.y, inv, bv.y), 0.f);
    r.z = fmaxf(fmaf(acc.z, inv, bv.z), 0.f);
    r.w = fmaxf(fmaf(acc.w, inv, bv.w), 0.f);
    *reinterpret_cast<float4*>(g_h + (size_t)v * 128 + lane * 4) = r;
}

__global__ void k_agg2(const float* __restrict__ att, const float* __restrict__ bias,
                       float* __restrict__ out, int n) {
    int v    = (blockIdx.x * blockDim.x + threadIdx.x) >> 5;
    int lane = threadIdx.x & 31;
    if (v >= n) return;

    const float2* xl2 = reinterpret_cast<const float2*>(g_xl2);
    float2 xrv  = *reinterpret_cast<const float2*>(g_xr2 + (size_t)v * 64 + lane * 2);
    float2 attv = *reinterpret_cast<const float2*>(att + lane * 2);
    float2 acc  = make_float2(0.f, 0.f);
    float  den  = 0.f;

    int s0 = g_rowptr[v], s1 = g_rowptr[v + 1];

    auto score = [&](const float2& xv) -> float {
        float s;
        s = lrelu(xv.x + xrv.x) * attv.x;
        s = fmaf(lrelu(xv.y + xrv.y), attv.y, s);
        #pragma unroll
        for (int off = 16; off; off >>= 1)
            s += __shfl_xor_sync(0xffffffffu, s, off);
        return __expf(s);
    };
    auto accum = [&](const float2& xv, float p) {
        den += p;
        acc.x = fmaf(p, xv.x, acc.x);
        acc.y = fmaf(p, xv.y, acc.y);
    };

    int j = s0;
    int nb4 = (s1 - s0) >> 2;
    if (nb4 > 0) {
        int i0 = g_col[j], i1 = g_col[j+1], i2 = g_col[j+2], i3 = g_col[j+3];
        float2 x0 = __ldg(&xl2[(size_t)i0 * 32 + lane]);
        float2 x1 = __ldg(&xl2[(size_t)i1 * 32 + lane]);
        float2 x2 = __ldg(&xl2[(size_t)i2 * 32 + lane]);
        float2 x3 = __ldg(&xl2[(size_t)i3 * 32 + lane]);
        for (int b = 1; b < nb4; b++) {
            j += 4;
            int n0 = g_col[j], n1 = g_col[j+1], n2 = g_col[j+2], n3 = g_col[j+3];
            float p0 = score(x0), p1 = score(x1), p2 = score(x2), p3 = score(x3);
            accum(x0, p0); accum(x1, p1); accum(x2, p2); accum(x3, p3);
            x0 = __ldg(&xl2[(size_t)n0 * 32 + lane]);
            x1 = __ldg(&xl2[(size_t)n1 * 32 + lane]);
            x2 = __ldg(&xl2[(size_t)n2 * 32 + lane]);
            x3 = __ldg(&xl2[(size_t)n3 * 32 + lane]);
        }
        float p0 = score(x0), p1 = score(x1), p2 = score(x2), p3 = score(x3);
        accum(x0, p0); accum(x1, p1); accum(x2, p2); accum(x3, p3);
        j += 4;
    }
    for (; j < s1; j++) {
        int src = g_col[j];
        float2 xv = __ldg(&xl2[(size_t)src * 32 + lane]);
        accum(xv, score(xv));
    }

    float2 bv = *reinterpret_cast<const float2*>(bias + lane * 2);
    float inv = 1.f / den;
    float2 r;
    r.x = fmaf(acc.x, inv, bv.x);
    r.y = fmaf(acc.y, inv, bv.y);
    *reinterpret_cast<float2*>(out + (size_t)v * 64 + lane * 2) = r;
}

// --------------------------- launch ----------------------------------------

extern "C" void kernel_launch(void* const* d_in, const int* in_sizes, int n_in,
                              void* d_out, int out_size) {
    const float* x     = (const float*)d_in[0];
    const int*   ei    = (const int*)d_in[1];
    const float* Wl1   = (const float*)d_in[2];
    const float* bl1   = (const float*)d_in[3];
    const float* Wr1   = (const float*)d_in[4];
    const float* br1   = (const float*)d_in[5];
    const float* att1  = (const float*)d_in[6];
    const float* bias1 = (const float*)d_in[7];
    const float* Wl2   = (const float*)d_in[8];
    const float* bl2   = (const float*)d_in[9];
    const float* Wr2   = (const float*)d_in[10];
    const float* br2   = (const float*)d_in[11];
    const float* att2  = (const float*)d_in[12];
    const float* bias2 = (const float*)d_in[13];
    float* out = (float*)d_out;

    int N = in_sizes[0] / 128;
    int E = in_sizes[1] / 2;
    int rb = (N + 127) / 128;
    int nvec = ((E & 3) == 0) ? (E >> 2) : 0;

    // 1. count, 2. scan (scan seeds self-loops, zeroes deg/cnt)
    {
        int th = nvec + (E - nvec * 4);
        k_count<<<(th + 255) / 256, 256>>>(ei + E, E, nvec);
    }
    k_scan<<<1, 1024>>>(N);

    // 3. fused layer-1 transform + CSR scatter (y: 4 gemm planes + 1 scatter)
    k_gemm2<0, 128, true><<<dim3(rb, 5), 128>>>(x, Wl1, Wr1, bl1, br1, N,
                                                ei, ei + E, E, nvec, N);

    // 4. layer-1 aggregation (+ReLU) -> g_h   [ncu capture slot]
    k_agg1<<<(N + 7) / 8, 256>>>(att1, bias1, N);

    // 5. layer-2 fused transform
    k_gemm2<1, 64, false><<<dim3(rb, 2), 128>>>(nullptr, Wl2, Wr2, bl2, br2, N,
                                                nullptr, nullptr, 0, 0, 0);

    // 6. layer-2 aggregation -> d_out
    k_agg2<<<(N + 7) / 8, 256>>>(att2, bias2, out, N);
}

// round 15
// speedup vs baseline: 1.0547x; 1.0547x over previous
#include <cuda_runtime.h>
#include <cstddef>

// ---------------------------------------------------------------------------
// GATv2 x2 on GB300.  kernel_launch = kernel launches ONLY.
// Order: count(1), scan(2), scatter(3), gemm1(4 = ncu slot), agg1(5),
// gemm2(6), agg2(7).  Scatter standalone (R14 fusion regressed).
// Scan folds self-loop seeding + deg/cnt zeroing (replay-invariant).
// Agg is issue-bound (R14: issue 59.9%) -> fmaxf-form lrelu (4 instr/ch)
// and 128-thread blocks (less degree-tail imbalance, 36 warps/SM).
// ---------------------------------------------------------------------------

#define NMAX 100000
#define EMAX 1700032

__device__ float g_xl1[NMAX * 128];
__device__ float g_xr1[NMAX * 128];
__device__ float g_h  [NMAX * 128];
__device__ float g_xl2[NMAX * 64];
__device__ float g_xr2[NMAX * 64];
__device__ int   g_deg[NMAX];      // zero at launch start (invariant)
__device__ int   g_cnt[NMAX];      // zeroed by scan before scatter
__device__ int   g_rowptr[NMAX + 1];
__device__ int   g_col[EMAX];

// --------------------------- CSR build -------------------------------------

__global__ void k_count(const int* __restrict__ dstE, int E, int nvec) {
    int t = blockIdx.x * blockDim.x + threadIdx.x;
    if (t < nvec) {
        int4 d = reinterpret_cast<const int4*>(dstE)[t];
        atomicAdd(&g_deg[d.x], 1);
        atomicAdd(&g_deg[d.y], 1);
        atomicAdd(&g_deg[d.z], 1);
        atomicAdd(&g_deg[d.w], 1);
    } else {
        int e = nvec * 4 + (t - nvec);
        if (e < E) atomicAdd(&g_deg[dstE[e]], 1);
    }
}

// exclusive scan of (deg+1) -> rowptr; zero deg & cnt afterwards.
__global__ void k_scan(int n) {
    __shared__ int wsum[32];
    __shared__ int carry;
    int t = threadIdx.x;
    if (t == 0) carry = 0;
    __syncthreads();
    for (int base = 0; base < n; base += 1024) {
        int i = base + t;
        int v = (i < n) ? (g_deg[i] + 1) : 0;    // +1 = self loop
        int x = v;
        #pragma unroll
        for (int off = 1; off < 32; off <<= 1) {
            int y = __shfl_up_sync(0xffffffffu, x, off);
            if ((t & 31) >= off) x += y;
        }
        if ((t & 31) == 31) wsum[t >> 5] = x;
        __syncthreads();
        if (t < 32) {
            int w = wsum[t];
            #pragma unroll
            for (int off = 1; off < 32; off <<= 1) {
                int y = __shfl_up_sync(0xffffffffu, w, off);
                if (t >= off) w += y;
            }
            wsum[t] = w;
        }
        __syncthreads();
        int incl = x + ((t >= 32) ? wsum[(t >> 5) - 1] : 0);
        if (i < n) {
            g_rowptr[i] = incl - v + carry;
            g_deg[i] = 0;
            g_cnt[i] = 0;
        }
        __syncthreads();
        if (t == 1023) carry += incl;
        __syncthreads();
    }
    if (t == 0) g_rowptr[n] = carry;
}

__device__ __forceinline__ void csr_place(int s, int d) {
    int pos = g_rowptr[d] + atomicAdd(&g_cnt[d], 1);
    g_col[pos] = s;
}

// threads: [0,nvec) vec edges; [nvec,nvec+N) self loops; then scalar tail
__global__ void k_scatter(const int* __restrict__ srcE,
                          const int* __restrict__ dstE, int E, int nvec, int N) {
    int t = blockIdx.x * blockDim.x + threadIdx.x;
    if (t < nvec) {
        int4 s = reinterpret_cast<const int4*>(srcE)[t];
        int4 d = reinterpret_cast<const int4*>(dstE)[t];
        csr_place(s.x, d.x);
        csr_place(s.y, d.y);
        csr_place(s.z, d.z);
        csr_place(s.w, d.w);
    } else {
        int u = t - nvec;
        if (u < N) {
            csr_place(u, u);
        } else {
            int e = nvec * 4 + (u - N);
            if (e < E) csr_place(srcE[e], dstE[e]);
        }
    }
}

// --------------------------- fused dense GEMM -------------------------------
// Computes BOTH xl = X@Wl+bl and xr = X@Wr+br in one launch.
// 128 threads/block, 8 rows x 8 cols per thread, interleaved rows.

template<int XSEL, int NOUT>
__global__ void __launch_bounds__(128, 4)
k_gemm2(const float* __restrict__ Xarg,
        const float* __restrict__ WL, const float* __restrict__ WR,
        const float* __restrict__ BL, const float* __restrict__ BR, int n) {
    constexpr int K = 128, KC = 64, NB = 64, TPR = 8;
    constexpr int RG = 128 / TPR;                        // 16 row groups
    constexpr int R = 8;
    constexpr int ROWS = RG * R;                         // 128 rows/block
    constexpr int CG = NOUT / NB;
    __shared__ float sW[KC][NB];          // 16 KB
    __shared__ float sx[ROWS][KC + 4];    // 34.8 KB

    const float* X = (XSEL == 0) ? Xarg : g_h;
    int lr = blockIdx.y / CG;
    int cg = blockIdx.y % CG;
    const float* W    = lr ? WR : WL;
    const float* Bias = lr ? BR : BL;
    float* Y;
    if constexpr (XSEL == 0) Y = lr ? g_xr1 : g_xl1;
    else                     Y = lr ? g_xr2 : g_xl2;

    int tid = threadIdx.x;
    int colOff = cg * NB;
    int c0 = (tid % TPR) * 4;
    int rg = tid / TPR;
    int base = blockIdx.x * ROWS;

    float4 bv0 = *reinterpret_cast<const float4*>(Bias + colOff + c0);
    float4 bv1 = *reinterpret_cast<const float4*>(Bias + colOff + c0 + 32);
    unsigned long long a0[R][2], a1[R][2];
    #pragma unroll
    for (int r = 0; r < R; r++) {
        asm("mov.b64 %0, {%1,%2};" : "=l"(a0[r][0]) : "f"(bv0.x), "f"(bv0.y));
        asm("mov.b64 %0, {%1,%2};" : "=l"(a0[r][1]) : "f"(bv0.z), "f"(bv0.w));
        asm("mov.b64 %0, {%1,%2};" : "=l"(a1[r][0]) : "f"(bv1.x), "f"(bv1.y));
        asm("mov.b64 %0, {%1,%2};" : "=l"(a1[r][1]) : "f"(bv1.z), "f"(bv1.w));
    }

    for (int kc = 0; kc < K; kc += KC) {
        __syncthreads();
        for (int i = tid; i < KC * NB / 4; i += 128) {
            int krow = (i * 4) / NB;
            int col  = (i * 4) % NB;
            *reinterpret_cast<float4*>(&sW[krow][col]) =
                *reinterpret_cast<const float4*>(W + (size_t)(kc + krow) * NOUT + colOff + col);
        }
        for (int i = tid; i < ROWS * (KC / 4); i += 128) {
            int r  = i / (KC / 4);
            int kk = (i % (KC / 4)) * 4;
            int row = base + r;
            float4 v = (row < n)
                ? *reinterpret_cast<const float4*>(X + (size_t)row * K + kc + kk)
                : make_float4(0.f, 0.f, 0.f, 0.f);
            *reinterpret_cast<float4*>(&sx[r][kk]) = v;
        }
        __syncthreads();
        #pragma unroll
        for (int k4 = 0; k4 < KC; k4 += 4) {
            float4 xv[R];
            #pragma unroll
            for (int r = 0; r < R; r++)
                xv[r] = *reinterpret_cast<const float4*>(&sx[rg + r * RG][k4]);
            #pragma unroll
            for (int kk = 0; kk < 4; kk++) {
                ulonglong2 w0 = *reinterpret_cast<const ulonglong2*>(&sW[k4 + kk][c0]);
                ulonglong2 w1 = *reinterpret_cast<const ulonglong2*>(&sW[k4 + kk][c0 + 32]);
                #pragma unroll
                for (int r = 0; r < R; r++) {
                    float xs = (kk == 0) ? xv[r].x : (kk == 1) ? xv[r].y
                             : (kk == 2) ? xv[r].z : xv[r].w;
                    unsigned long long x2;
                    asm("mov.b64 %0, {%1,%1};" : "=l"(x2) : "f"(xs));
                    asm("fma.rn.f32x2 %0, %1, %2, %0;" : "+l"(a0[r][0]) : "l"(x2), "l"(w0.x));
                    asm("fma.rn.f32x2 %0, %1, %2, %0;" : "+l"(a0[r][1]) : "l"(x2), "l"(w0.y));
                    asm("fma.rn.f32x2 %0, %1, %2, %0;" : "+l"(a1[r][0]) : "l"(x2), "l"(w1.x));
                    asm("fma.rn.f32x2 %0, %1, %2, %0;" : "+l"(a1[r][1]) : "l"(x2), "l"(w1.y));
                }
            }
        }
    }

    #pragma unroll
    for (int r = 0; r < R; r++) {
        int row = base + rg + r * RG;
        if (row < n) {
            float t0, t1, t2, t3;
            asm("mov.b64 {%0,%1}, %2;" : "=f"(t0), "=f"(t1) : "l"(a0[r][0]));
            asm("mov.b64 {%0,%1}, %2;" : "=f"(t2), "=f"(t3) : "l"(a0[r][1]));
            *reinterpret_cast<float4*>(Y + (size_t)row * NOUT + colOff + c0) =
                make_float4(t0, t1, t2, t3);
            asm("mov.b64 {%0,%1}, %2;" : "=f"(t0), "=f"(t1) : "l"(a1[r][0]));
            asm("mov.b64 {%0,%1}, %2;" : "=f"(t2), "=f"(t3) : "l"(a1[r][1]));
            *reinterpret_cast<float4*>(Y + (size_t)row * NOUT + colOff + c0 + 32) =
                make_float4(t0, t1, t2, t3);
        }
    }
}

// --------------------------- GATv2 aggregation ------------------------------
// Warp per destination node, software-pipelined gathers.
// lrelu via fmaxf(e, 0.2e): exact for slope<1, compiles to FADD+FMUL+FMNMX
// (no FSETP/SEL) — agg is issue-bound so instruction count is the lever.
// Scores O(+-10) (glorot x unit-normal): exp without max-pass is safe.

__device__ __forceinline__ float lrelu(float e) {
    return fmaxf(e, 0.2f * e);
}

__global__ void k_agg1(const float* __restrict__ att, const float* __restrict__ bias,
                       int n) {
    int v    = (blockIdx.x * blockDim.x + threadIdx.x) >> 5;
    int lane = threadIdx.x & 31;
    if (v >= n) return;

    const float4* xl4 = reinterpret_cast<const float4*>(g_xl1);
    float4 xrv  = *reinterpret_cast<const float4*>(g_xr1 + (size_t)v * 128 + lane * 4);
    float4 attv = *reinterpret_cast<const float4*>(att + lane * 4);
    float4 acc  = make_float4(0.f, 0.f, 0.f, 0.f);
    float  den  = 0.f;

    int s0 = g_rowptr[v], s1 = g_rowptr[v + 1];

    auto score = [&](const float4& xv) -> float {
        float s;
        s = lrelu(xv.x + xrv.x) * attv.x;
        s = fmaf(lrelu(xv.y + xrv.y), attv.y, s);
        s = fmaf(lrelu(xv.z + xrv.z), attv.z, s);
        s = fmaf(lrelu(xv.w + xrv.w), attv.w, s);
        s += __shfl_xor_sync(0xffffffffu, s, 1);
        s += __shfl_xor_sync(0xffffffffu, s, 2);
        s += __shfl_xor_sync(0xffffffffu, s, 4);
        return __expf(s);
    };
    auto accum = [&](const float4& xv, float p) {
        den += p;
        acc.x = fmaf(p, xv.x, acc.x);
        acc.y = fmaf(p, xv.y, acc.y);
        acc.z = fmaf(p, xv.z, acc.z);
        acc.w = fmaf(p, xv.w, acc.w);
    };

    int j = s0;
    int nb4 = (s1 - s0) >> 2;
    if (nb4 > 0) {
        int i0 = g_col[j], i1 = g_col[j+1], i2 = g_col[j+2], i3 = g_col[j+3];
        float4 x0 = __ldg(&xl4[(size_t)i0 * 32 + lane]);
        float4 x1 = __ldg(&xl4[(size_t)i1 * 32 + lane]);
        float4 x2 = __ldg(&xl4[(size_t)i2 * 32 + lane]);
        float4 x3 = __ldg(&xl4[(size_t)i3 * 32 + lane]);
        for (int b = 1; b < nb4; b++) {
            j += 4;
            int n0 = g_col[j], n1 = g_col[j+1], n2 = g_col[j+2], n3 = g_col[j+3];
            float p0 = score(x0), p1 = score(x1), p2 = score(x2), p3 = score(x3);
            accum(x0, p0); accum(x1, p1); accum(x2, p2); accum(x3, p3);
            x0 = __ldg(&xl4[(size_t)n0 * 32 + lane]);
            x1 = __ldg(&xl4[(size_t)n1 * 32 + lane]);
            x2 = __ldg(&xl4[(size_t)n2 * 32 + lane]);
            x3 = __ldg(&xl4[(size_t)n3 * 32 + lane]);
        }
        float p0 = score(x0), p1 = score(x1), p2 = score(x2), p3 = score(x3);
        accum(x0, p0); accum(x1, p1); accum(x2, p2); accum(x3, p3);
        j += 4;
    }
    for (; j < s1; j++) {
        int src = g_col[j];
        float4 xv = __ldg(&xl4[(size_t)src * 32 + lane]);
        accum(xv, score(xv));
    }

    float4 bv = *reinterpret_cast<const float4*>(bias + lane * 4);
    float inv = 1.f / den;
    float4 r;
    r.x = fmaxf(fmaf(acc.x, inv, bv.x), 0.f);
    r.y = fmaxf(fmaf(acc.y, inv, bv.y), 0.f);
    r.z = fmaxf(fmaf(acc.z, inv, bv.z), 0.f);
    r.w = fmaxf(fmaf(acc.w, inv, bv.w), 0.f);
    *reinterpret_cast<float4*>(g_h + (size_t)v * 128 + lane * 4) = r;
}

__global__ void k_agg2(const float* __restrict__ att, const float* __restrict__ bias,
                       float* __restrict__ out, int n) {
    int v    = (blockIdx.x * blockDim.x + threadIdx.x) >> 5;
    int lane = threadIdx.x & 31;
    if (v >= n) return;

    const float2* xl2 = reinterpret_cast<const float2*>(g_xl2);
    float2 xrv  = *reinterpret_cast<const float2*>(g_xr2 + (size_t)v * 64 + lane * 2);
    float2 attv = *reinterpret_cast<const float2*>(att + lane * 2);
    float2 acc  = make_float2(0.f, 0.f);
    float  den  = 0.f;

    int s0 = g_rowptr[v], s1 = g_rowptr[v + 1];

    auto score = [&](const float2& xv) -> float {
        float s;
        s = lrelu(xv.x + xrv.x) * attv.x;
        s = fmaf(lrelu(xv.y + xrv.y), attv.y, s);
        #pragma unroll
        for (int off = 16; off; off >>= 1)
            s += __shfl_xor_sync(0xffffffffu, s, off);
        return __expf(s);
    };
    auto accum = [&](const float2& xv, float p) {
        den += p;
        acc.x = fmaf(p, xv.x, acc.x);
        acc.y = fmaf(p, xv.y, acc.y);
    };

    int j = s0;
    int nb4 = (s1 - s0) >> 2;
    if (nb4 > 0) {
        int i0 = g_col[j], i1 = g_col[j+1], i2 = g_col[j+2], i3 = g_col[j+3];
        float2 x0 = __ldg(&xl2[(size_t)i0 * 32 + lane]);
        float2 x1 = __ldg(&xl2[(size_t)i1 * 32 + lane]);
        float2 x2 = __ldg(&xl2[(size_t)i2 * 32 + lane]);
        float2 x3 = __ldg(&xl2[(size_t)i3 * 32 + lane]);
        for (int b = 1; b < nb4; b++) {
            j += 4;
            int n0 = g_col[j], n1 = g_col[j+1], n2 = g_col[j+2], n3 = g_col[j+3];
            float p0 = score(x0), p1 = score(x1), p2 = score(x2), p3 = score(x3);
            accum(x0, p0); accum(x1, p1); accum(x2, p2); accum(x3, p3);
            x0 = __ldg(&xl2[(size_t)n0 * 32 + lane]);
            x1 = __ldg(&xl2[(size_t)n1 * 32 + lane]);
            x2 = __ldg(&xl2[(size_t)n2 * 32 + lane]);
            x3 = __ldg(&xl2[(size_t)n3 * 32 + lane]);
        }
        float p0 = score(x0), p1 = score(x1), p2 = score(x2), p3 = score(x3);
        accum(x0, p0); accum(x1, p1); accum(x2, p2); accum(x3, p3);
        j += 4;
    }
    for (; j < s1; j++) {
        int src = g_col[j];
        float2 xv = __ldg(&xl2[(size_t)src * 32 + lane]);
        accum(xv, score(xv));
    }

    float2 bv = *reinterpret_cast<const float2*>(bias + lane * 2);
    float inv = 1.f / den;
    float2 r;
    r.x = fmaf(acc.x, inv, bv.x);
    r.y = fmaf(acc.y, inv, bv.y);
    *reinterpret_cast<float2*>(out + (size_t)v * 64 + lane * 2) = r;
}

// --------------------------- launch ----------------------------------------

extern "C" void kernel_launch(void* const* d_in, const int* in_sizes, int n_in,
                              void* d_out, int out_size) {
    const float* x     = (const float*)d_in[0];
    const int*   ei    = (const int*)d_in[1];
    const float* Wl1   = (const float*)d_in[2];
    const float* bl1   = (const float*)d_in[3];
    const float* Wr1   = (const float*)d_in[4];
    const float* br1   = (const float*)d_in[5];
    const float* att1  = (const float*)d_in[6];
    const float* bias1 = (const float*)d_in[7];
    const float* Wl2   = (const float*)d_in[8];
    const float* bl2   = (const float*)d_in[9];
    const float* Wr2   = (const float*)d_in[10];
    const float* br2   = (const float*)d_in[11];
    const float* att2  = (const float*)d_in[12];
    const float* bias2 = (const float*)d_in[13];
    float* out = (float*)d_out;

    int N = in_sizes[0] / 128;
    int E = in_sizes[1] / 2;
    int rb = (N + 127) / 128;
    int nvec = ((E & 3) == 0) ? (E >> 2) : 0;

    // 1. count, 2. scan, 3. scatter
    {
        int th = nvec + (E - nvec * 4);
        k_count<<<(th + 255) / 256, 256>>>(ei + E, E, nvec);
    }
    k_scan<<<1, 1024>>>(N);
    {
        int th = nvec + N + (E - nvec * 4);
        k_scatter<<<(th + 255) / 256, 256>>>(ei, ei + E, E, nvec, N);
    }

    // 4. layer-1 fused transform  [ncu capture slot]
    k_gemm2<0, 128><<<dim3(rb, 4), 128>>>(x, Wl1, Wr1, bl1, br1, N);

    // 5. layer-1 aggregation (+ReLU) -> g_h
    k_agg1<<<(N + 3) / 4, 128>>>(att1, bias1, N);

    // 6. layer-2 fused transform
    k_gemm2<1, 64><<<dim3(rb, 2), 128>>>(nullptr, Wl2, Wr2, bl2, br2, N);

    // 7. layer-2 aggregation -> d_out
    k_agg2<<<(N + 3) / 4, 128>>>(att2, bias2, out, N);
}